// round 8
// baseline (speedup 1.0000x reference)
#include <cuda_runtime.h>
#include <cstdint>

// VQ argmin, bit-replicating the reference fp32 arithmetic (verified rel_err==0):
//   A_n  = sum_i fl(z[n,i]^2)            (fp32, sequential mul+add)
//   B_nk = fold_i fmaf(z[n,i], e[k,i])   (fp32, sequential FMA, i ascending)
//   C_k  = sum_i fl(e[k,i]^2)            (fp32, sequential mul+add)
//   d_nk = fl( fl(A - 2B) + C );  out[n] = argmin_k (ties -> lowest k), as float
//   NOTE: fl(2B) is EXACT (x2 = exponent bump), so FFMA(-2,B,A) == fl(A-2B)
//   bit-identically -> single FFMA is safe in the epilogue.
//
// R8: occupancy/balance fix. R7 ran 256 blocks on 148 SMs -> 1-2 blocks/SM
// (occ 11.3%, issue 61%). Now 444 blocks (exactly 3/SM at 168 regs = 12 warps)
// tile-stride over 512 point-tiles. Core math unchanged.

#define D        64
#define KCODES   512
#define TPB      128
#define P        2
#define CHUNK    128
#define NCHUNK   (KCODES / CHUNK)
#define GRID     444          // 3 blocks per SM on 148 SMs
#define PTS_PER_TILE (TPB * P)

__global__ void __launch_bounds__(TPB, 3)
vq_kernel(const float* __restrict__ z,
          const float* __restrict__ cb,
          void* __restrict__ out,
          int npoints,
          int out_is_f64)
{
    __shared__ float scb[CHUNK * D];   // 32 KB: one codebook chunk
    __shared__ float sC[KCODES];       // 2 KB: ||e_k||^2

    const int tid = threadIdx.x;

    // ---- C[k]: fp32 sequential sum of fl(e_i^2) (once per block) ----
    for (int k = tid; k < KCODES; k += TPB) {
        const float* e = cb + k * D;
        float c = 0.0f;
        #pragma unroll
        for (int i = 0; i < D; i++)
            c = __fadd_rn(c, __fmul_rn(e[i], e[i]));
        sC[k] = c;
    }

    const int ntiles = (npoints + PTS_PER_TILE - 1) / PTS_PER_TILE;   // 512

    for (int tile = blockIdx.x; tile < ntiles; tile += GRID) {
        const int base = tile * PTS_PER_TILE + tid;

        int  pidx[P];
        bool act[P];
        #pragma unroll
        for (int j = 0; j < P; j++) {
            pidx[j] = base + j * TPB;
            act[j]  = (pidx[j] < npoints);
        }

        // ---- Load P points into registers ----
        float zr[P][D];
        #pragma unroll
        for (int j = 0; j < P; j++) {
            if (act[j]) {
                const float4* zp = reinterpret_cast<const float4*>(z + (size_t)pidx[j] * D);
                #pragma unroll
                for (int i = 0; i < D / 4; i++) {
                    float4 v = zp[i];
                    zr[j][4*i+0] = v.x; zr[j][4*i+1] = v.y;
                    zr[j][4*i+2] = v.z; zr[j][4*i+3] = v.w;
                }
            } else {
                #pragma unroll
                for (int i = 0; i < D; i++) zr[j][i] = 0.0f;
            }
        }

        // ---- A: fp32 sequential sum of fl(z_i^2) (mul then add, NOT fma) ----
        float a[P];
        #pragma unroll
        for (int j = 0; j < P; j++) {
            float s = 0.0f;
            #pragma unroll
            for (int i = 0; i < D; i++)
                s = __fadd_rn(s, __fmul_rn(zr[j][i], zr[j][i]));
            a[j] = s;
        }

        float bestd[P];
        int   bestk[P];
        #pragma unroll
        for (int j = 0; j < P; j++) { bestd[j] = __int_as_float(0x7f800000); bestk[j] = 0; }

        for (int ch = 0; ch < NCHUNK; ch++) {
            __syncthreads();   // previous chunk / previous tile fully consumed
            {   // stage 128 codes into smem, coalesced float4
                const float4* src = reinterpret_cast<const float4*>(cb + ch * CHUNK * D);
                float4*       dst = reinterpret_cast<float4*>(scb);
                #pragma unroll
                for (int i = tid; i < CHUNK * D / 4; i += TPB)
                    dst[i] = src[i];
            }
            __syncthreads();

            #pragma unroll 1
            for (int k0 = 0; k0 < CHUNK; k0 += 2) {
                // 2 codes x P=2 points = 4 independent sequential FMA chains.
                float b00 = 0.0f, b01 = 0.0f, b10 = 0.0f, b11 = 0.0f;
                const float4* e0 = reinterpret_cast<const float4*>(scb + (k0+0) * D);
                const float4* e1 = reinterpret_cast<const float4*>(scb + (k0+1) * D);

                // Software-pipelined: prefetch next i's e-vectors.
                float4 u = e0[0];
                float4 v = e1[0];
                #pragma unroll
                for (int i = 0; i < D / 4; i++) {
                    float4 un, vn;
                    if (i < D / 4 - 1) { un = e0[i + 1]; vn = e1[i + 1]; }
                    b00 = __fmaf_rn(zr[0][4*i+0], u.x, b00);
                    b10 = __fmaf_rn(zr[1][4*i+0], u.x, b10);
                    b01 = __fmaf_rn(zr[0][4*i+0], v.x, b01);
                    b11 = __fmaf_rn(zr[1][4*i+0], v.x, b11);
                    b00 = __fmaf_rn(zr[0][4*i+1], u.y, b00);
                    b10 = __fmaf_rn(zr[1][4*i+1], u.y, b10);
                    b01 = __fmaf_rn(zr[0][4*i+1], v.y, b01);
                    b11 = __fmaf_rn(zr[1][4*i+1], v.y, b11);
                    b00 = __fmaf_rn(zr[0][4*i+2], u.z, b00);
                    b10 = __fmaf_rn(zr[1][4*i+2], u.z, b10);
                    b01 = __fmaf_rn(zr[0][4*i+2], v.z, b01);
                    b11 = __fmaf_rn(zr[1][4*i+2], v.z, b11);
                    b00 = __fmaf_rn(zr[0][4*i+3], u.w, b00);
                    b10 = __fmaf_rn(zr[1][4*i+3], u.w, b10);
                    b01 = __fmaf_rn(zr[0][4*i+3], v.w, b01);
                    b11 = __fmaf_rn(zr[1][4*i+3], v.w, b11);
                    if (i < D / 4 - 1) { u = un; v = vn; }
                }

                const int gk = ch * CHUNK + k0;
                const float c0 = sC[gk + 0];
                const float c1 = sC[gk + 1];
                // fl(A-2B) via one FFMA (exact: 2B is a power-of-two multiply).
                float d00 = __fadd_rn(__fmaf_rn(-2.0f, b00, a[0]), c0);
                float d01 = __fadd_rn(__fmaf_rn(-2.0f, b01, a[0]), c1);
                float d10 = __fadd_rn(__fmaf_rn(-2.0f, b10, a[1]), c0);
                float d11 = __fadd_rn(__fmaf_rn(-2.0f, b11, a[1]), c1);
                if (d00 < bestd[0]) { bestd[0] = d00; bestk[0] = gk + 0; }
                if (d01 < bestd[0]) { bestd[0] = d01; bestk[0] = gk + 1; }
                if (d10 < bestd[1]) { bestd[1] = d10; bestk[1] = gk + 0; }
                if (d11 < bestd[1]) { bestd[1] = d11; bestk[1] = gk + 1; }
            }
        }

        #pragma unroll
        for (int j = 0; j < P; j++) {
            if (act[j]) {
                if (out_is_f64) ((double*)out)[pidx[j]] = (double)bestk[j];
                else            ((float*)out)[pidx[j]]  = (float)bestk[j];
            }
        }
    }
}

extern "C" void kernel_launch(void* const* d_in, const int* in_sizes, int n_in,
                              void* d_out, int out_size) {
    // Identify z (bigger) vs codebook (smaller) — holds for bytes or elements.
    long long s0 = in_sizes[0];
    long long s1 = (n_in >= 2) ? in_sizes[1] : 0;
    const float* z;
    const float* cb;
    long long zsize, cbsize;
    if (s1 > s0) {
        cb = (const float*)d_in[0]; cbsize = s0;
        z  = (const float*)d_in[1]; zsize  = s1;
    } else {
        z  = (const float*)d_in[0]; zsize  = s0;
        cb = (const float*)d_in[1]; cbsize = s1;
    }

    // Unit inference: codebook is exactly KCODES*D = 32768 ELEMENTS.
    long long scale = cbsize / (KCODES * D);
    if (scale < 1) scale = 1;

    const int npoints = (int)(zsize / ((long long)D * scale));   // 131072

    const long long bpp = (npoints > 0) ? ((long long)out_size) / npoints : 1;
    const int out_is_f64 = (bpp == 8) ? 1 : 0;

    vq_kernel<<<GRID, TPB>>>(z, cb, d_out, npoints, out_is_f64);
}